// round 15
// baseline (speedup 1.0000x reference)
#include <cuda_runtime.h>
#include <cuda_bf16.h>
#include <math_constants.h>
#include <cstdint>

// ---------------- problem constants ----------------
#define BATCH 32
#define TSEQ  256
#define CEMB  384
#define NHEAD 6
#define HS    64
#define M_TOT (BATCH*TSEQ)        // 8192
#define WELEM (CEMB*CEMB)         // 147456
#define QKV_ELEM (M_TOT*CEMB)     // 3145728

__device__ __forceinline__ uint32_t smem_u32(const void* p) {
    uint32_t a;
    asm("{ .reg .u64 t; cvta.to.shared.u64 t, %1; cvt.u32.u64 %0, t; }" : "=r"(a) : "l"(p));
    return a;
}
#define LDSM4(r, addr) \
    asm volatile("ldmatrix.sync.aligned.m8n8.x4.shared.b16 {%0,%1,%2,%3}, [%4];" \
        : "=r"((r)[0]), "=r"((r)[1]), "=r"((r)[2]), "=r"((r)[3]) : "r"(addr))

__device__ __forceinline__ void mma_bf16(float* c, const uint32_t* a, uint32_t b0, uint32_t b1) {
    asm volatile("mma.sync.aligned.m16n8k16.row.col.f32.bf16.bf16.f32 "
        "{%0,%1,%2,%3}, {%4,%5,%6,%7}, {%8,%9}, {%0,%1,%2,%3};"
        : "+f"(c[0]), "+f"(c[1]), "+f"(c[2]), "+f"(c[3])
        : "r"(a[0]), "r"(a[1]), "r"(a[2]), "r"(a[3]), "r"(b0), "r"(b1));
}
__device__ __forceinline__ float quant8m(float v, float inv) {
    return fminf(fmaxf(rintf(v * inv), -128.0f), 127.0f);
}
__device__ __forceinline__ uint32_t pkbf(float a, float b) {
    __nv_bfloat162 t = __floats2bfloat162_rn(a, b);
    return *reinterpret_cast<uint32_t*>(&t);
}

// ---------------- device scratch (static — no allocation) ----------------
// g_wmax/g_hmax only updated via atomicMax with input-determined values:
// graph replays are idempotent (zero-init at load, stable thereafter).
__device__ unsigned g_wmax[4];
__device__ unsigned g_hmax[18];
__device__ float    g_bsf[4];
__device__ float    g_bint[4*CEMB];
__device__ __align__(16) __nv_bfloat16 g_wb[4*WELEM];   // quantized weights, bf16 (exact)
__device__ __align__(16) __nv_bfloat16 g_xh[QKV_ELEM];  // x_int hi split
__device__ __align__(16) __nv_bfloat16 g_xl[QKV_ELEM];  // x_int lo split
__device__ __align__(16) __nv_bfloat16 g_x2h[QKV_ELEM]; // attn-out x_int hi split
__device__ __align__(16) __nv_bfloat16 g_x2l[QKV_ELEM]; // attn-out x_int lo split
__device__ float    g_qkvf[3*QKV_ELEM];    // [mat][B][H][T][HS] float q,k,v

// ---------------- per-matrix max|W| ----------------
__global__ void k_wmax(const float* __restrict__ Wq, const float* __restrict__ Wk,
                       const float* __restrict__ Wv, const float* __restrict__ Wp) {
    int mat = blockIdx.x / 144;
    int j   = (blockIdx.x % 144) * 1024 + threadIdx.x * 4;
    const float* W = mat==0?Wq : mat==1?Wk : mat==2?Wv : Wp;
    float4 w = *(const float4*)(W + j);
    float v = fmaxf(fmaxf(fabsf(w.x), fabsf(w.y)), fmaxf(fabsf(w.z), fabsf(w.w)));
    #pragma unroll
    for (int o = 16; o; o >>= 1) v = fmaxf(v, __shfl_xor_sync(0xffffffffu, v, o));
    __shared__ float sm[8];
    if ((threadIdx.x & 31) == 0) sm[threadIdx.x >> 5] = v;
    __syncthreads();
    if (threadIdx.x < 8) {
        v = sm[threadIdx.x];
        #pragma unroll
        for (int o = 4; o; o >>= 1) v = fmaxf(v, __shfl_xor_sync(0x000000ffu, v, o));
        if (threadIdx.x == 0) atomicMax(&g_wmax[mat], __float_as_uint(v));
    }
}

// ---------------- fused pre-GEMM: weight quant + bias quant + x hi/lo split ----------
__global__ void k_pre(const float* __restrict__ x, const float* __restrict__ xsf,
                      const float* __restrict__ Wq, const float* __restrict__ bq,
                      const float* __restrict__ Wk, const float* __restrict__ bk,
                      const float* __restrict__ Wv, const float* __restrict__ bv,
                      const float* __restrict__ Wp, const float* __restrict__ bp) {
    int bid = blockIdx.x, tid = threadIdx.x;
    if (bid < 288) {
        int mat = bid / 72, sub = bid % 72;
        int j = sub * 2048 + tid * 8;
        const float* W = mat==0?Wq : mat==1?Wk : mat==2?Wv : Wp;
        float wsf = fmaxf(__uint_as_float(g_wmax[mat]), 1e-8f) / 127.0f;
        float winv = 1.0f / wsf;
        __nv_bfloat162* wp = (__nv_bfloat162*)(g_wb + (size_t)mat*WELEM + j);
        #pragma unroll
        for (int h = 0; h < 2; h++) {
            float4 w = *(const float4*)(W + j + h*4);
            wp[2*h]   = __floats2bfloat162_rn(quant8m(w.x, winv), quant8m(w.y, winv));
            wp[2*h+1] = __floats2bfloat162_rn(quant8m(w.z, winv), quant8m(w.w, winv));
        }
        if (sub < 2) {
            float asf = (mat == 3) ? (1.0f/256.0f) : xsf[0];
            float bsf = wsf * asf;
            if (sub == 0 && tid == 0) g_bsf[mat] = bsf;
            const float* b = mat==0?bq : mat==1?bk : mat==2?bv : bp;
            int n = sub*256 + tid;
            if (n < 384) {
                float bi = rintf(b[n] / bsf);   // exact div: global constant path
                bi = fminf(fmaxf(bi, -2147483648.0f), 2147483647.0f);
                g_bint[mat*CEMB + n] = bi;
            }
        }
    } else {
        int i = (bid - 288) * 2048 + tid * 8;
        float inv = 1.0f / xsf[0];
        #pragma unroll
        for (int h = 0; h < 2; h++) {
            float4 xv = *(const float4*)(x + i + h*4);
            float x0 = xv.x * inv, x1 = xv.y * inv, x2 = xv.z * inv, x3 = xv.w * inv;
            __nv_bfloat162 h01 = __floats2bfloat162_rn(x0, x1);
            __nv_bfloat162 h23 = __floats2bfloat162_rn(x2, x3);
            ((__nv_bfloat162*)(g_xh + i + h*4))[0] = h01;
            ((__nv_bfloat162*)(g_xh + i + h*4))[1] = h23;
            ((__nv_bfloat162*)(g_xl + i + h*4))[0] = __floats2bfloat162_rn(
                x0 - __bfloat162float(h01.x), x1 - __bfloat162float(h01.y));
            ((__nv_bfloat162*)(g_xl + i + h*4))[1] = __floats2bfloat162_rn(
                x2 - __bfloat162float(h23.x), x3 - __bfloat162float(h23.y));
        }
    }
}

// ---------------- HMMA bf16 GEMM, cp.async pipelined, 2 CTA/SM ----------------------
#define CHB 16384
#define SB_BOF 32768
#define SB_BINT 65536
#define SM_TOT (65536 + 1024)
__global__ void __launch_bounds__(256) k_tgemm(int mode, float* __restrict__ Out, int out_size) {
    extern __shared__ char smem[];
    int tid = threadIdx.x, warp = tid >> 5, lane = tid & 31;
    int bm = blockIdx.y * 128, n0 = blockIdx.x * 128;

    const __nv_bfloat16* Ah = (mode ? g_x2h : g_xh) + (size_t)bm*384;
    const __nv_bfloat16* Al = (mode ? g_x2l : g_xl) + (size_t)bm*384;
    const __nv_bfloat16* Wb = g_wb + (mode ? (size_t)3*WELEM : 0) + (size_t)n0*384;

    float* sb_bint = (float*)(smem + SB_BINT);
    unsigned* smax = (unsigned*)(smem + SB_BINT + 512);
    if (tid < 128) sb_bint[tid] = g_bint[(mode ? 3*CEMB : 0) + n0 + tid];
    if (tid < 2) smax[tid] = 0u;

    uint32_t sbA = smem_u32(smem);
    uint32_t sbB = sbA + SB_BOF;

    auto stageB = [&](int cb) {
        #pragma unroll
        for (int r = 0; r < 4; r++) {
            int i = tid + r*256;
            int row = i >> 3, k8 = i & 7;
            uint32_t d = sbB + (cb & 1)*CHB + row*128 + ((k8*16) ^ ((row & 7) << 4));
            const void* s = Wb + (size_t)row*384 + cb*64 + k8*8;
            asm volatile("cp.async.cg.shared.global [%0], [%1], 16;" :: "r"(d), "l"(s));
        }
    };
    auto stageA = [&](int t) {
        int cb = t >> 1;
        const __nv_bfloat16* src = ((t & 1) ? Al : Ah) + cb*64;
        uint32_t dst = sbA + (t & 1)*CHB;
        #pragma unroll
        for (int r = 0; r < 4; r++) {
            int i = tid + r*256;
            int row = i >> 3, k8 = i & 7;
            uint32_t d = dst + row*128 + ((k8*16) ^ ((row & 7) << 4));
            const void* s = src + (size_t)row*384 + k8*8;
            asm volatile("cp.async.cg.shared.global [%0], [%1], 16;" :: "r"(d), "l"(s));
        }
    };

    stageB(0); stageA(0);
    asm volatile("cp.async.commit_group;" ::: "memory");
    stageA(1);
    asm volatile("cp.async.commit_group;" ::: "memory");

    int wm = (warp & 3) << 5;
    int wn = (warp >> 2) << 6;
    int quad = lane >> 3, lrow = lane & 7;

    uint32_t a_row[2], a_pat[2], b_row[4], b_pat[4];
    #pragma unroll
    for (int mt = 0; mt < 2; mt++) {
        int r = wm + mt*16 + ((quad & 1) << 3) + lrow;
        a_row[mt] = r*128; a_pat[mt] = (r & 7) << 4;
    }
    #pragma unroll
    for (int bt = 0; bt < 4; bt++) {
        int r = wn + bt*16 + ((quad >> 1) << 3) + lrow;
        b_row[bt] = r*128; b_pat[bt] = (r & 7) << 4;
    }
    int kqA = (quad >> 1) << 4;
    int kqB = (quad & 1) << 4;

    float acc[2][8][4];
    #pragma unroll
    for (int i = 0; i < 2; i++)
        #pragma unroll
        for (int j = 0; j < 8; j++)
            #pragma unroll
            for (int l = 0; l < 4; l++) acc[i][j][l] = 0.0f;

    #pragma unroll 1
    for (int t = 0; t < 12; t++) {
        if (t < 11) asm volatile("cp.async.wait_group 1;" ::: "memory");
        else        asm volatile("cp.async.wait_group 0;" ::: "memory");
        __syncthreads();
        uint32_t Ab = sbA + (t & 1)*CHB;
        uint32_t Bb = sbB + ((t >> 1) & 1)*CHB;
        #pragma unroll
        for (int ks = 0; ks < 4; ks++) {
            int ka = ks*32 + kqA, kb = ks*32 + kqB;
            uint32_t a[2][4], b[4][4];
            LDSM4(a[0], Ab + a_row[0] + (ka ^ a_pat[0]));
            LDSM4(a[1], Ab + a_row[1] + (ka ^ a_pat[1]));
            #pragma unroll
            for (int bt = 0; bt < 4; bt++)
                LDSM4(b[bt], Bb + b_row[bt] + (kb ^ b_pat[bt]));
            #pragma unroll
            for (int mt = 0; mt < 2; mt++)
                #pragma unroll
                for (int bt = 0; bt < 4; bt++) {
                    mma_bf16(acc[mt][bt*2],   a[mt], b[bt][0], b[bt][1]);
                    mma_bf16(acc[mt][bt*2+1], a[mt], b[bt][2], b[bt][3]);
                }
        }
        __syncthreads();
        int nt = t + 2;
        if (nt < 12) {
            if ((nt & 1) == 0) stageB(nt >> 1);
            stageA(nt);
            asm volatile("cp.async.commit_group;" ::: "memory");
        }
    }

    float bsf = mode ? g_bsf[3] : g_bsf[n0 / 384];
    float* stg = (float*)smem;
    int mat = 0, h0 = 0;
    if (mode == 0) { mat = n0 / 384; h0 = (n0 % 384) >> 6; }
    float lmax = 0.0f;
    int hl = (tid & 31) >> 4;

    #pragma unroll
    for (int hf = 0; hf < 2; hf++) {
        #pragma unroll
        for (int mt = 0; mt < 2; mt++) {
            int rbase = wm + mt*16;
            if ((rbase >> 6) == hf) {
                int r0 = (rbase & 63) + (lane >> 2);
                #pragma unroll
                for (int nt = 0; nt < 8; nt++) {
                    int c = wn + nt*8 + ((lane & 3) << 1);
                    float b0 = sb_bint[c], b1 = sb_bint[c+1];
                    stg[r0*132 + c]       = (acc[mt][nt][0] + b0) * bsf;
                    stg[r0*132 + c + 1]   = (acc[mt][nt][1] + b1) * bsf;
                    stg[(r0+8)*132 + c]   = (acc[mt][nt][2] + b0) * bsf;
                    stg[(r0+8)*132 + c+1] = (acc[mt][nt][3] + b1) * bsf;
                }
            }
        }
        __syncthreads();
        for (int i = tid; i < 2048; i += 256) {
            int row = i >> 5, c4 = (i & 31) << 2;
            const float* sp = stg + row*132 + c4;
            float v0 = sp[0], v1 = sp[1], v2 = sp[2], v3 = sp[3];
            int m = bm + hf*64 + row;
            if (mode == 0) {
                lmax = fmaxf(lmax, fmaxf(fmaxf(fabsf(v0), fabsf(v1)), fmaxf(fabsf(v2), fabsf(v3))));
                int c = (n0 + c4) % 384;
                int h = c >> 6, d = c & 63;
                int b_ = m >> 8, t = m & 255;
                *(float4*)(g_qkvf + (size_t)mat*QKV_ELEM + (((size_t)(b_*6 + h))*256 + t)*64 + d)
                    = make_float4(v0, v1, v2, v3);
            } else {
                *(float4*)(Out + (size_t)m*384 + n0 + c4) = make_float4(v0, v1, v2, v3);
            }
        }
        __syncthreads();
    }
    if (mode == 0) {
        atomicMax(&smax[hl], __float_as_uint(lmax));
        __syncthreads();
        if (tid < 2) atomicMax(&g_hmax[mat*6 + h0 + tid], smax[tid]);
    }
    if (mode == 1 && out_size > QKV_ELEM && blockIdx.x == 0 && blockIdx.y == 0 && tid == 0)
        Out[QKV_ELEM] = g_bsf[3];
}

// ---------------- HMMA attention: 128-row blocks, 512 threads, 16 warps -------------
// grid (2,6,32): warps = 8 m-tiles x 2 key-halves. tile = 1-bx (heavy first).
// smem: Q[128x144] K[256x144] V^T[64x528] rm/rs[2x128] ob[128x65] (overlays K region).
#define AQ  0
#define AK  18432
#define AV  55296
#define ARM 89088
#define ARS 90112
#define AOB 18432
#define AT_TOT 91136
__global__ void __launch_bounds__(512) k_attn() {
    extern __shared__ char sm[];
    uint32_t smb = smem_u32(sm);
    int tid = threadIdx.x, warp = tid >> 5, lane = tid & 31;
    int b = blockIdx.z, hd = blockIdx.y, tile = 1 - blockIdx.x;
    int mw = warp & 7, th = warp >> 3;
    int kend = (tile + 1) * 128;
    size_t slab = (size_t)(b*6 + hd) * 16384;
    const float* qg = g_qkvf + slab + (size_t)tile*8192;
    const float* kg = g_qkvf + QKV_ELEM + slab;
    const float* vg = g_qkvf + 2*(size_t)QKV_ELEM + slab;

    float qsf = fmaxf(__uint_as_float(g_hmax[hd]),      1e-8f) / 127.0f;
    float ksf = fmaxf(__uint_as_float(g_hmax[6 + hd]),  1e-8f) / 127.0f;
    float vsf = fmaxf(__uint_as_float(g_hmax[12 + hd]), 1e-8f) / 127.0f;
    float qiv = 1.0f / qsf, kiv = 1.0f / ksf, viv = 1.0f / vsf;
    float sf  = __fmul_rn(ksf, qsf);
    const float C0 = 0.35815147f;
    const float C1 = (float)(0.96963238 / 0.35815147);
    const float C2 = (float)(1.0 / 0.35815147);
    float x0i   = floorf(-0.6931f / sf);
    float bi    = floorf(C1 / sf);
    float sf2   = __fmul_rn(sf, sf);
    float ci    = floorf(C2 / sf2);
    float expsf = __fmul_rn(C0, sf2) * (1.0f/1073741824.0f);
    float peak  = floorf(__fmul_rn(ci, 1073741824.0f)) * expsf;
    float s16   = fmaxf(peak, 1e-8f) / 32767.0f;
    float osc   = vsf * (1.0f/256.0f);
    float clampv = 30.0f * x0i;
    float ix0   = 1.0f / x0i;
    float es16  = expsf / s16;

    // Q: 128x64 -> integer-valued bf16, rows padded to 144B
    for (int i = tid; i < 2048; i += 512) {
        int row = i >> 4, c4 = i & 15;
        float4 v = *(const float4*)(qg + row*64 + c4*4);
        uint2 o;
        o.x = pkbf(quant8m(v.x, qiv), quant8m(v.y, qiv));
        o.y = pkbf(quant8m(v.z, qiv), quant8m(v.w, qiv));
        *(uint2*)(sm + AQ + row*144 + c4*8) = o;
    }
    // K: kend x 64
    for (int i = tid; i < kend*16; i += 512) {
        int row = i >> 4, c4 = i & 15;
        float4 v = *(const float4*)(kg + row*64 + c4*4);
        uint2 o;
        o.x = pkbf(quant8m(v.x, kiv), quant8m(v.y, kiv));
        o.y = pkbf(quant8m(v.z, kiv), quant8m(v.w, kiv));
        *(uint2*)(sm + AK + row*144 + c4*8) = o;
    }
    // V transposed [d][t], rows padded to 528B
    for (int i = tid; i < kend*16; i += 512) {
        int t = i >> 4, c = i & 15;
        #pragma unroll
        for (int j = 0; j < 4; j++) {
            int d = j*16 + c;
            float v = vg[t*64 + d];
            *(__nv_bfloat16*)(sm + AV + d*528 + t*2) = __float2bfloat16(quant8m(v, viv));
        }
    }
    __syncthreads();

    int quad = lane >> 3, lrow = lane & 7;
    int ktiles = kend >> 3;          // 16 or 32
    int half = ktiles >> 1;          // 8 or 16 (block-uniform)
    int kbase = th * half * 8;       // key-row offset for this half
    int npair = half >> 1;           // 4 or 8

    uint32_t af[4][4];
    {
        int r = mw*16 + ((quad & 1) << 3) + lrow;
        uint32_t base = smb + AQ + r*144 + ((quad >> 1) << 4);
        #pragma unroll
        for (int kc = 0; kc < 4; kc++) LDSM4(af[kc], base + kc*32);
    }

    float acc[16][4];
    #pragma unroll
    for (int i = 0; i < 16; i++)
        #pragma unroll
        for (int e = 0; e < 4; e++) acc[i][e] = 0.0f;

    #pragma unroll
    for (int np = 0; np < 8; np++) {
        if (np < npair) {
            int r = kbase + np*16 + ((quad >> 1) << 3) + lrow;
            uint32_t base = smb + AK + r*144 + ((quad & 1) << 4);
            #pragma unroll
            for (int kc = 0; kc < 4; kc++) {
                uint32_t bf[4];
                LDSM4(bf, base + kc*32);
                mma_bf16(acc[np*2],   af[kc], bf[0], bf[1]);
                mma_bf16(acc[np*2+1], af[kc], bf[2], bf[3]);
            }
        }
    }

    // mask + scale + row max
    int g = lane >> 2;
    int row0 = mw*16 + g, row1 = row0 + 8;
    int grow0 = tile*128 + row0, grow1 = grow0 + 8;
    float rmax0 = -CUDART_INF_F, rmax1 = -CUDART_INF_F;
    #pragma unroll
    for (int nt = 0; nt < 16; nt++) {
        if (nt < half) {
            int kb = kbase + nt*8 + ((lane & 3) << 1);
            float x0 = (kb   <= grow0) ? acc[nt][0]*0.125f : -CUDART_INF_F;
            float x1 = (kb+1 <= grow0) ? acc[nt][1]*0.125f : -CUDART_INF_F;
            float x2 = (kb   <= grow1) ? acc[nt][2]*0.125f : -CUDART_INF_F;
            float x3 = (kb+1 <= grow1) ? acc[nt][3]*0.125f : -CUDART_INF_F;
            acc[nt][0]=x0; acc[nt][1]=x1; acc[nt][2]=x2; acc[nt][3]=x3;
            rmax0 = fmaxf(rmax0, fmaxf(x0, x1));
            rmax1 = fmaxf(rmax1, fmaxf(x2, x3));
        }
    }
    rmax0 = fmaxf(rmax0, __shfl_xor_sync(0xffffffffu, rmax0, 1));
    rmax0 = fmaxf(rmax0, __shfl_xor_sync(0xffffffffu, rmax0, 2));
    rmax1 = fmaxf(rmax1, __shfl_xor_sync(0xffffffffu, rmax1, 1));
    rmax1 = fmaxf(rmax1, __shfl_xor_sync(0xffffffffu, rmax1, 2));
    float* rm = (float*)(sm + ARM);
    if ((lane & 3) == 0) { rm[th*128 + row0] = rmax0; rm[th*128 + row1] = rmax1; }
    __syncthreads();
    rmax0 = fmaxf(rm[row0], rm[128 + row0]);
    rmax1 = fmaxf(rm[row1], rm[128 + row1]);

    // IntSoftmax (validated scalar sequence)
    float sum0 = 0.0f, sum1 = 0.0f;
    #pragma unroll
    for (int nt = 0; nt < 16; nt++) {
        if (nt < half) {
            #pragma unroll
            for (int e = 0; e < 4; e++) {
                float x = fmaxf(acc[nt][e] - ((e < 2) ? rmax0 : rmax1), clampv);
                float qf = floorf(x * ix0);
                float r  = x - __fmul_rn(x0i, qf);
                float z  = __fadd_rn(__fmul_rn(__fadd_rn(r, bi), r), ci);
                int   n  = 30 - (int)qf;
                float e2 = __int_as_float((n + 127) << 23);
                float ei = fmaxf(floorf(__fmul_rn(z, e2)), 0.0f);
                float t  = fminf(rintf(ei * es16), 32767.0f);
                acc[nt][e] = t;
                if (e < 2) sum0 += t; else sum1 += t;
            }
        }
    }
    sum0 += __shfl_xor_sync(0xffffffffu, sum0, 1);
    sum0 += __shfl_xor_sync(0xffffffffu, sum0, 2);
    sum1 += __shfl_xor_sync(0xffffffffu, sum1, 1);
    sum1 += __shfl_xor_sync(0xffffffffu, sum1, 2);
    float* rs = (float*)(sm + ARS);
    if ((lane & 3) == 0) { rs[th*128 + row0] = sum0; rs[th*128 + row1] = sum1; }
    __syncthreads();
    float fac0 = floorf(4294967296.0f / (rs[row0] + rs[128 + row0]));
    float fac1 = floorf(4294967296.0f / (rs[row1] + rs[128 + row1]));

    // P @ V
    float oacc[8][4];
    #pragma unroll
    for (int i = 0; i < 8; i++)
        #pragma unroll
        for (int e = 0; e < 4; e++) oacc[i][e] = 0.0f;

    #pragma unroll
    for (int j = 0; j < 8; j++) {
        if (j < npair) {
            uint32_t pa[4];
            pa[0] = pkbf(floorf(__fmul_rn(acc[2*j][0],   fac0) * (1.0f/16777216.0f)),
                         floorf(__fmul_rn(acc[2*j][1],   fac0) * (1.0f/16777216.0f)));
            pa[1] = pkbf(floorf(__fmul_rn(acc[2*j][2],   fac1) * (1.0f/16777216.0f)),
                         floorf(__fmul_rn(acc[2*j][3],   fac1) * (1.0f/16777216.0f)));
            pa[2] = pkbf(floorf(__fmul_rn(acc[2*j+1][0], fac0) * (1.0f/16777216.0f)),
                         floorf(__fmul_rn(acc[2*j+1][1], fac0) * (1.0f/16777216.0f)));
            pa[3] = pkbf(floorf(__fmul_rn(acc[2*j+1][2], fac1) * (1.0f/16777216.0f)),
                         floorf(__fmul_rn(acc[2*j+1][3], fac1) * (1.0f/16777216.0f)));
            int tb2 = (kbase + j*16)*2 + ((quad & 1) << 4);
            #pragma unroll
            for (int dt = 0; dt < 4; dt++) {
                int dr = dt*16 + ((quad >> 1) << 3) + lrow;
                uint32_t vb[4];
                LDSM4(vb, smb + AV + dr*528 + tb2);
                mma_bf16(oacc[dt*2],   pa, vb[0], vb[1]);
                mma_bf16(oacc[dt*2+1], pa, vb[2], vb[3]);
            }
        }
    }

    // cross-half O reduction (ob overlays dead K region) + split-store output
    __syncthreads();   // all warps done reading K/V smem before overlay write
    float* ob = (float*)(sm + AOB);   // [128][65]
    if (th == 1) {
        #pragma unroll
        for (int nt = 0; nt < 8; nt++) {
            int d = nt*8 + ((lane & 3) << 1);
            ob[row0*65 + d]     = oacc[nt][0];
            ob[row0*65 + d + 1] = oacc[nt][1];
            ob[row1*65 + d]     = oacc[nt][2];
            ob[row1*65 + d + 1] = oacc[nt][3];
        }
    }
    __syncthreads();
    if (th == 0) {
        int m0 = b*256 + tile*128 + row0;
        int m1 = m0 + 8;
        #pragma unroll
        for (int nt = 0; nt < 8; nt++) {
            int d = nt*8 + ((lane & 3) << 1);
            float o0 = (oacc[nt][0] + ob[row0*65 + d])     * osc;
            float o1 = (oacc[nt][1] + ob[row0*65 + d + 1]) * osc;
            float o2 = (oacc[nt][2] + ob[row1*65 + d])     * osc;
            float o3 = (oacc[nt][3] + ob[row1*65 + d + 1]) * osc;
            __nv_bfloat162 hp0 = __floats2bfloat162_rn(o0, o1);
            __nv_bfloat162 lp0 = __floats2bfloat162_rn(o0 - __bfloat162float(hp0.x),
                                                       o1 - __bfloat162float(hp0.y));
            __nv_bfloat162 hp1 = __floats2bfloat162_rn(o2, o3);
            __nv_bfloat162 lp1 = __floats2bfloat162_rn(o2 - __bfloat162float(hp1.x),
                                                       o3 - __bfloat162float(hp1.y));
            *(__nv_bfloat162*)(g_x2h + (size_t)m0*384 + hd*64 + d) = hp0;
            *(__nv_bfloat162*)(g_x2l + (size_t)m0*384 + hd*64 + d) = lp0;
            *(__nv_bfloat162*)(g_x2h + (size_t)m1*384 + hd*64 + d) = hp1;
            *(__nv_bfloat162*)(g_x2l + (size_t)m1*384 + hd*64 + d) = lp1;
        }
    }
}

// ---------------- launch ----------------
extern "C" void kernel_launch(void* const* d_in, const int* in_sizes, int n_in,
                              void* d_out, int out_size) {
    (void)in_sizes; (void)n_in;
    const float* x   = (const float*)d_in[0];
    const float* xsf = (const float*)d_in[1];
    const float* Wq  = (const float*)d_in[2];
    const float* bq  = (const float*)d_in[3];
    const float* Wk  = (const float*)d_in[4];
    const float* bk  = (const float*)d_in[5];
    const float* Wv  = (const float*)d_in[6];
    const float* bv  = (const float*)d_in[7];
    const float* Wp  = (const float*)d_in[8];
    const float* bp  = (const float*)d_in[9];
    float* out = (float*)d_out;

    cudaFuncSetAttribute(k_tgemm, cudaFuncAttributeMaxDynamicSharedMemorySize, SM_TOT);
    cudaFuncSetAttribute(k_attn,  cudaFuncAttributeMaxDynamicSharedMemorySize, AT_TOT);

    k_wmax<<<576, 256>>>(Wq, Wk, Wv, Wp);
    k_pre<<<1824, 256>>>(x, xsf, Wq, bq, Wk, bk, Wv, bv, Wp, bp);
    k_tgemm<<<dim3(9, 64), 256, SM_TOT>>>(0, out, out_size);   // q,k,v projections
    k_attn<<<dim3(2, 6, 32), 512, AT_TOT>>>();                 // HMMA attention (16 warps)
    k_tgemm<<<dim3(3, 64), 256, SM_TOT>>>(1, out, out_size);   // output projection
}

// round 16
// speedup vs baseline: 1.0207x; 1.0207x over previous
#include <cuda_runtime.h>
#include <cuda_bf16.h>
#include <math_constants.h>
#include <cstdint>

// ---------------- problem constants ----------------
#define BATCH 32
#define TSEQ  256
#define CEMB  384
#define NHEAD 6
#define HS    64
#define M_TOT (BATCH*TSEQ)        // 8192
#define WELEM (CEMB*CEMB)         // 147456
#define QKV_ELEM (M_TOT*CEMB)     // 3145728

__device__ __forceinline__ uint32_t smem_u32(const void* p) {
    uint32_t a;
    asm("{ .reg .u64 t; cvta.to.shared.u64 t, %1; cvt.u32.u64 %0, t; }" : "=r"(a) : "l"(p));
    return a;
}
#define LDSM4(r, addr) \
    asm volatile("ldmatrix.sync.aligned.m8n8.x4.shared.b16 {%0,%1,%2,%3}, [%4];" \
        : "=r"((r)[0]), "=r"((r)[1]), "=r"((r)[2]), "=r"((r)[3]) : "r"(addr))

__device__ __forceinline__ void mma_bf16(float* c, const uint32_t* a, uint32_t b0, uint32_t b1) {
    asm volatile("mma.sync.aligned.m16n8k16.row.col.f32.bf16.bf16.f32 "
        "{%0,%1,%2,%3}, {%4,%5,%6,%7}, {%8,%9}, {%0,%1,%2,%3};"
        : "+f"(c[0]), "+f"(c[1]), "+f"(c[2]), "+f"(c[3])
        : "r"(a[0]), "r"(a[1]), "r"(a[2]), "r"(a[3]), "r"(b0), "r"(b1));
}
__device__ __forceinline__ float quant8m(float v, float inv) {
    return fminf(fmaxf(rintf(v * inv), -128.0f), 127.0f);
}
__device__ __forceinline__ uint32_t pkbf(float a, float b) {
    __nv_bfloat162 t = __floats2bfloat162_rn(a, b);
    return *reinterpret_cast<uint32_t*>(&t);
}

// ---------------- device scratch (static — no allocation) ----------------
// g_wmax/g_hmax only updated via atomicMax with input-determined values:
// graph replays are idempotent (zero-init at load, stable thereafter).
__device__ unsigned g_wmax[4];
__device__ unsigned g_hmax[18];
__device__ float    g_bsf[4];
__device__ float    g_bint[4*CEMB];
__device__ __align__(16) __nv_bfloat16 g_wb[4*WELEM];   // quantized weights, bf16 (exact)
__device__ __align__(16) __nv_bfloat16 g_xh[QKV_ELEM];  // x_int hi split
__device__ __align__(16) __nv_bfloat16 g_xl[QKV_ELEM];  // x_int lo split
__device__ __align__(16) __nv_bfloat16 g_x2h[QKV_ELEM]; // attn-out x_int hi split
__device__ __align__(16) __nv_bfloat16 g_x2l[QKV_ELEM]; // attn-out x_int lo split
__device__ float    g_qkvf[3*QKV_ELEM];    // [mat][B][H][T][HS] float q,k,v

// ---------------- per-matrix max|W| ----------------
__global__ void k_wmax(const float* __restrict__ Wq, const float* __restrict__ Wk,
                       const float* __restrict__ Wv, const float* __restrict__ Wp) {
    int mat = blockIdx.x / 144;
    int j   = (blockIdx.x % 144) * 1024 + threadIdx.x * 4;
    const float* W = mat==0?Wq : mat==1?Wk : mat==2?Wv : Wp;
    float4 w = *(const float4*)(W + j);
    float v = fmaxf(fmaxf(fabsf(w.x), fabsf(w.y)), fmaxf(fabsf(w.z), fabsf(w.w)));
    #pragma unroll
    for (int o = 16; o; o >>= 1) v = fmaxf(v, __shfl_xor_sync(0xffffffffu, v, o));
    __shared__ float sm[8];
    if ((threadIdx.x & 31) == 0) sm[threadIdx.x >> 5] = v;
    __syncthreads();
    if (threadIdx.x < 8) {
        v = sm[threadIdx.x];
        #pragma unroll
        for (int o = 4; o; o >>= 1) v = fmaxf(v, __shfl_xor_sync(0x000000ffu, v, o));
        if (threadIdx.x == 0) atomicMax(&g_wmax[mat], __float_as_uint(v));
    }
}

// ---------------- fused pre-GEMM: weight quant + bias quant + x hi/lo split ----------
__global__ void k_pre(const float* __restrict__ x, const float* __restrict__ xsf,
                      const float* __restrict__ Wq, const float* __restrict__ bq,
                      const float* __restrict__ Wk, const float* __restrict__ bk,
                      const float* __restrict__ Wv, const float* __restrict__ bv,
                      const float* __restrict__ Wp, const float* __restrict__ bp) {
    int bid = blockIdx.x, tid = threadIdx.x;
    if (bid < 288) {
        int mat = bid / 72, sub = bid % 72;
        int j = sub * 2048 + tid * 8;
        const float* W = mat==0?Wq : mat==1?Wk : mat==2?Wv : Wp;
        float wsf = fmaxf(__uint_as_float(g_wmax[mat]), 1e-8f) / 127.0f;
        float winv = 1.0f / wsf;
        __nv_bfloat162* wp = (__nv_bfloat162*)(g_wb + (size_t)mat*WELEM + j);
        #pragma unroll
        for (int h = 0; h < 2; h++) {
            float4 w = *(const float4*)(W + j + h*4);
            wp[2*h]   = __floats2bfloat162_rn(quant8m(w.x, winv), quant8m(w.y, winv));
            wp[2*h+1] = __floats2bfloat162_rn(quant8m(w.z, winv), quant8m(w.w, winv));
        }
        if (sub < 2) {
            float asf = (mat == 3) ? (1.0f/256.0f) : xsf[0];
            float bsf = wsf * asf;
            if (sub == 0 && tid == 0) g_bsf[mat] = bsf;
            const float* b = mat==0?bq : mat==1?bk : mat==2?bv : bp;
            int n = sub*256 + tid;
            if (n < 384) {
                float bi = rintf(b[n] / bsf);   // exact div: global constant path
                bi = fminf(fmaxf(bi, -2147483648.0f), 2147483647.0f);
                g_bint[mat*CEMB + n] = bi;
            }
        }
    } else {
        int i = (bid - 288) * 2048 + tid * 8;
        float inv = 1.0f / xsf[0];
        #pragma unroll
        for (int h = 0; h < 2; h++) {
            float4 xv = *(const float4*)(x + i + h*4);
            float x0 = xv.x * inv, x1 = xv.y * inv, x2 = xv.z * inv, x3 = xv.w * inv;
            __nv_bfloat162 h01 = __floats2bfloat162_rn(x0, x1);
            __nv_bfloat162 h23 = __floats2bfloat162_rn(x2, x3);
            ((__nv_bfloat162*)(g_xh + i + h*4))[0] = h01;
            ((__nv_bfloat162*)(g_xh + i + h*4))[1] = h23;
            ((__nv_bfloat162*)(g_xl + i + h*4))[0] = __floats2bfloat162_rn(
                x0 - __bfloat162float(h01.x), x1 - __bfloat162float(h01.y));
            ((__nv_bfloat162*)(g_xl + i + h*4))[1] = __floats2bfloat162_rn(
                x2 - __bfloat162float(h23.x), x3 - __bfloat162float(h23.y));
        }
    }
}

// ---------------- HMMA bf16 GEMM, cp.async pipelined, 2 CTA/SM ----------------------
// K=768 walked as (B0:A0h,A0l)(B1:A1h,A1l)...: B double-buffered 2x16KB, A TRIPLE-
// buffered 3x16KB (prefetch distance 2 never collides with the buffer being read),
// so only ONE __syncthreads per chunk. smem 83KB -> 2 CTA/SM.
#define CHB 16384
#define SB_BOF 49152
#define SB_BINT 81920
#define SM_TOT (81920 + 1024)
__global__ void __launch_bounds__(256) k_tgemm(int mode, float* __restrict__ Out, int out_size) {
    extern __shared__ char smem[];
    int tid = threadIdx.x, warp = tid >> 5, lane = tid & 31;
    int bm = blockIdx.y * 128, n0 = blockIdx.x * 128;

    const __nv_bfloat16* Ah = (mode ? g_x2h : g_xh) + (size_t)bm*384;
    const __nv_bfloat16* Al = (mode ? g_x2l : g_xl) + (size_t)bm*384;
    const __nv_bfloat16* Wb = g_wb + (mode ? (size_t)3*WELEM : 0) + (size_t)n0*384;

    float* sb_bint = (float*)(smem + SB_BINT);
    unsigned* smax = (unsigned*)(smem + SB_BINT + 512);
    if (tid < 128) sb_bint[tid] = g_bint[(mode ? 3*CEMB : 0) + n0 + tid];
    if (tid < 2) smax[tid] = 0u;

    uint32_t sbA = smem_u32(smem);
    uint32_t sbB = sbA + SB_BOF;

    auto stageB = [&](int cb) {       // B chunk cb -> buf cb&1
        #pragma unroll
        for (int r = 0; r < 4; r++) {
            int i = tid + r*256;
            int row = i >> 3, k8 = i & 7;
            uint32_t d = sbB + (cb & 1)*CHB + row*128 + ((k8*16) ^ ((row & 7) << 4));
            const void* s = Wb + (size_t)row*384 + cb*64 + k8*8;
            asm volatile("cp.async.cg.shared.global [%0], [%1], 16;" :: "r"(d), "l"(s));
        }
    };
    auto stageA = [&](int t) {        // virtual chunk t -> buf t%3
        int cb = t >> 1;
        const __nv_bfloat16* src = ((t & 1) ? Al : Ah) + cb*64;
        uint32_t dst = sbA + (t % 3)*CHB;
        #pragma unroll
        for (int r = 0; r < 4; r++) {
            int i = tid + r*256;
            int row = i >> 3, k8 = i & 7;
            uint32_t d = dst + row*128 + ((k8*16) ^ ((row & 7) << 4));
            const void* s = src + (size_t)row*384 + k8*8;
            asm volatile("cp.async.cg.shared.global [%0], [%1], 16;" :: "r"(d), "l"(s));
        }
    };

    stageB(0); stageA(0);
    asm volatile("cp.async.commit_group;" ::: "memory");
    stageA(1);
    asm volatile("cp.async.commit_group;" ::: "memory");

    int wm = (warp & 3) << 5;
    int wn = (warp >> 2) << 6;
    int quad = lane >> 3, lrow = lane & 7;

    uint32_t a_row[2], a_pat[2], b_row[4], b_pat[4];
    #pragma unroll
    for (int mt = 0; mt < 2; mt++) {
        int r = wm + mt*16 + ((quad & 1) << 3) + lrow;
        a_row[mt] = r*128; a_pat[mt] = (r & 7) << 4;
    }
    #pragma unroll
    for (int bt = 0; bt < 4; bt++) {
        int r = wn + bt*16 + ((quad >> 1) << 3) + lrow;
        b_row[bt] = r*128; b_pat[bt] = (r & 7) << 4;
    }
    int kqA = (quad >> 1) << 4;
    int kqB = (quad & 1) << 4;

    float acc[2][8][4];
    #pragma unroll
    for (int i = 0; i < 2; i++)
        #pragma unroll
        for (int j = 0; j < 8; j++)
            #pragma unroll
            for (int l = 0; l < 4; l++) acc[i][j][l] = 0.0f;

    #pragma unroll 1
    for (int t = 0; t < 12; t++) {
        if (t < 11) asm volatile("cp.async.wait_group 1;" ::: "memory");
        else        asm volatile("cp.async.wait_group 0;" ::: "memory");
        __syncthreads();              // single barrier per chunk (triple-buffered A)
        uint32_t Ab = sbA + (t % 3)*CHB;
        uint32_t Bb = sbB + ((t >> 1) & 1)*CHB;
        #pragma unroll
        for (int ks = 0; ks < 4; ks++) {
            int ka = ks*32 + kqA, kb = ks*32 + kqB;
            uint32_t a[2][4], b[4][4];
            LDSM4(a[0], Ab + a_row[0] + (ka ^ a_pat[0]));
            LDSM4(a[1], Ab + a_row[1] + (ka ^ a_pat[1]));
            #pragma unroll
            for (int bt = 0; bt < 4; bt++)
                LDSM4(b[bt], Bb + b_row[bt] + (kb ^ b_pat[bt]));
            #pragma unroll
            for (int mt = 0; mt < 2; mt++)
                #pragma unroll
                for (int bt = 0; bt < 4; bt++) {
                    mma_bf16(acc[mt][bt*2],   a[mt], b[bt][0], b[bt][1]);
                    mma_bf16(acc[mt][bt*2+1], a[mt], b[bt][2], b[bt][3]);
                }
        }
        int nt = t + 2;
        if (nt < 12) {
            if ((nt & 1) == 0) stageB(nt >> 1);
            stageA(nt);
            asm volatile("cp.async.commit_group;" ::: "memory");
        }
    }
    __syncthreads();   // all compute done before epilogue overwrites A buffers

    // epilogue in two 64-row halves (staging 64x132 floats = 33KB over A buffers)
    float bsf = mode ? g_bsf[3] : g_bsf[n0 / 384];
    float* stg = (float*)smem;
    int mat = 0, h0 = 0;
    if (mode == 0) { mat = n0 / 384; h0 = (n0 % 384) >> 6; }
    float lmax = 0.0f;
    int hl = (tid & 31) >> 4;

    #pragma unroll
    for (int hf = 0; hf < 2; hf++) {
        #pragma unroll
        for (int mt = 0; mt < 2; mt++) {
            int rbase = wm + mt*16;
            if ((rbase >> 6) == hf) {
                int r0 = (rbase & 63) + (lane >> 2);
                #pragma unroll
                for (int nt = 0; nt < 8; nt++) {
                    int c = wn + nt*8 + ((lane & 3) << 1);
                    float b0 = sb_bint[c], b1 = sb_bint[c+1];
                    stg[r0*132 + c]       = (acc[mt][nt][0] + b0) * bsf;
                    stg[r0*132 + c + 1]   = (acc[mt][nt][1] + b1) * bsf;
                    stg[(r0+8)*132 + c]   = (acc[mt][nt][2] + b0) * bsf;
                    stg[(r0+8)*132 + c+1] = (acc[mt][nt][3] + b1) * bsf;
                }
            }
        }
        __syncthreads();
        for (int i = tid; i < 2048; i += 256) {
            int row = i >> 5, c4 = (i & 31) << 2;
            const float* sp = stg + row*132 + c4;
            float v0 = sp[0], v1 = sp[1], v2 = sp[2], v3 = sp[3];
            int m = bm + hf*64 + row;
            if (mode == 0) {
                lmax = fmaxf(lmax, fmaxf(fmaxf(fabsf(v0), fabsf(v1)), fmaxf(fabsf(v2), fabsf(v3))));
                int c = (n0 + c4) % 384;
                int h = c >> 6, d = c & 63;
                int b_ = m >> 8, t = m & 255;
                *(float4*)(g_qkvf + (size_t)mat*QKV_ELEM + (((size_t)(b_*6 + h))*256 + t)*64 + d)
                    = make_float4(v0, v1, v2, v3);
            } else {
                *(float4*)(Out + (size_t)m*384 + n0 + c4) = make_float4(v0, v1, v2, v3);
            }
        }
        __syncthreads();
    }
    if (mode == 0) {
        atomicMax(&smax[hl], __float_as_uint(lmax));
        __syncthreads();
        if (tid < 2) atomicMax(&g_hmax[mat*6 + h0 + tid], smax[tid]);
    }
    if (mode == 1 && out_size > QKV_ELEM && blockIdx.x == 0 && blockIdx.y == 0 && tid == 0)
        Out[QKV_ELEM] = g_bsf[3];
}

// ---------------- HMMA attention (R14 proven-best: 64-row blocks, 8 warps) ----------
#define AT_QS 0
#define AT_KS 9216
#define AT_VT 46080
#define AT_RM 79872
#define AT_RS 80384
#define AT_OB 80896
#define AT_TOT 97536
__global__ void __launch_bounds__(256) k_attn() {
    extern __shared__ char sm[];
    uint32_t smb = smem_u32(sm);
    int tid = threadIdx.x, warp = tid >> 5, lane = tid & 31;
    int b = blockIdx.z, hd = blockIdx.y, tile = 3 - blockIdx.x;
    int mw = warp & 3, th = warp >> 2;
    int kend = (tile + 1) * 64;
    size_t slab = (size_t)(b*6 + hd) * 16384;
    const float* qg = g_qkvf + slab + (size_t)tile*4096;
    const float* kg = g_qkvf + QKV_ELEM + slab;
    const float* vg = g_qkvf + 2*(size_t)QKV_ELEM + slab;

    float qsf = fmaxf(__uint_as_float(g_hmax[hd]),      1e-8f) / 127.0f;
    float ksf = fmaxf(__uint_as_float(g_hmax[6 + hd]),  1e-8f) / 127.0f;
    float vsf = fmaxf(__uint_as_float(g_hmax[12 + hd]), 1e-8f) / 127.0f;
    float qiv = 1.0f / qsf, kiv = 1.0f / ksf, viv = 1.0f / vsf;
    float sf  = __fmul_rn(ksf, qsf);
    const float C0 = 0.35815147f;
    const float C1 = (float)(0.96963238 / 0.35815147);
    const float C2 = (float)(1.0 / 0.35815147);
    float x0i   = floorf(-0.6931f / sf);
    float bi    = floorf(C1 / sf);
    float sf2   = __fmul_rn(sf, sf);
    float ci    = floorf(C2 / sf2);
    float expsf = __fmul_rn(C0, sf2) * (1.0f/1073741824.0f);
    float peak  = floorf(__fmul_rn(ci, 1073741824.0f)) * expsf;
    float s16   = fmaxf(peak, 1e-8f) / 32767.0f;
    float osc   = vsf * (1.0f/256.0f);
    float clampv = 30.0f * x0i;
    float ix0   = 1.0f / x0i;
    float es16  = expsf / s16;

    for (int i = tid; i < 1024; i += 256) {
        int row = i >> 4, c4 = i & 15;
        float4 v = *(const float4*)(qg + row*64 + c4*4);
        uint2 o;
        o.x = pkbf(quant8m(v.x, qiv), quant8m(v.y, qiv));
        o.y = pkbf(quant8m(v.z, qiv), quant8m(v.w, qiv));
        *(uint2*)(sm + AT_QS + row*144 + c4*8) = o;
    }
    for (int i = tid; i < kend*16; i += 256) {
        int row = i >> 4, c4 = i & 15;
        float4 v = *(const float4*)(kg + row*64 + c4*4);
        uint2 o;
        o.x = pkbf(quant8m(v.x, kiv), quant8m(v.y, kiv));
        o.y = pkbf(quant8m(v.z, kiv), quant8m(v.w, kiv));
        *(uint2*)(sm + AT_KS + row*144 + c4*8) = o;
    }
    for (int i = tid; i < kend*16; i += 256) {
        int t = i >> 4, c = i & 15;
        #pragma unroll
        for (int j = 0; j < 4; j++) {
            int d = j*16 + c;
            float v = vg[t*64 + d];
            *(__nv_bfloat16*)(sm + AT_VT + d*528 + t*2) = __float2bfloat16(quant8m(v, viv));
        }
    }
    __syncthreads();

    int quad = lane >> 3, lrow = lane & 7;
    int ntiles = (kend >> 3) - th*16;
    ntiles = ntiles < 0 ? 0 : (ntiles > 16 ? 16 : ntiles);
    int npair = ntiles >> 1;

    uint32_t af[4][4];
    {
        int r = mw*16 + ((quad & 1) << 3) + lrow;
        uint32_t base = smb + AT_QS + r*144 + ((quad >> 1) << 4);
        #pragma unroll
        for (int kc = 0; kc < 4; kc++) LDSM4(af[kc], base + kc*32);
    }

    float acc[16][4];
    #pragma unroll
    for (int i = 0; i < 16; i++)
        #pragma unroll
        for (int e = 0; e < 4; e++) acc[i][e] = 0.0f;

    #pragma unroll
    for (int np = 0; np < 8; np++) {
        if (np < npair) {
            int r = th*128 + np*16 + ((quad >> 1) << 3) + lrow;
            uint32_t base = smb + AT_KS + r*144 + ((quad & 1) << 4);
            #pragma unroll
            for (int kc = 0; kc < 4; kc++) {
                uint32_t bf[4];
                LDSM4(bf, base + kc*32);
                mma_bf16(acc[np*2],   af[kc], bf[0], bf[1]);
                mma_bf16(acc[np*2+1], af[kc], bf[2], bf[3]);
            }
        }
    }

    int g = lane >> 2;
    int row0 = mw*16 + g, row1 = row0 + 8;
    int grow0 = tile*64 + row0, grow1 = grow0 + 8;
    float rmax0 = -CUDART_INF_F, rmax1 = -CUDART_INF_F;
    #pragma unroll
    for (int nt = 0; nt < 16; nt++) {
        if (nt < ntiles) {
            int kb = th*128 + nt*8 + ((lane & 3) << 1);
            float x0 = (kb   <= grow0) ? acc[nt][0]*0.125f : -CUDART_INF_F;
            float x1 = (kb+1 <= grow0) ? acc[nt][1]*0.125f : -CUDART_INF_F;
            float x2 = (kb   <= grow1) ? acc[nt][2]*0.125f : -CUDART_INF_F;
            float x3 = (kb+1 <= grow1) ? acc[nt][3]*0.125f : -CUDART_INF_F;
            acc[nt][0]=x0; acc[nt][1]=x1; acc[nt][2]=x2; acc[nt][3]=x3;
            rmax0 = fmaxf(rmax0, fmaxf(x0, x1));
            rmax1 = fmaxf(rmax1, fmaxf(x2, x3));
        }
    }
    rmax0 = fmaxf(rmax0, __shfl_xor_sync(0xffffffffu, rmax0, 1));
    rmax0 = fmaxf(rmax0, __shfl_xor_sync(0xffffffffu, rmax0, 2));
    rmax1 = fmaxf(rmax1, __shfl_xor_sync(0xffffffffu, rmax1, 1));
    rmax1 = fmaxf(rmax1, __shfl_xor_sync(0xffffffffu, rmax1, 2));
    float* rm = (float*)(sm + AT_RM);
    if ((lane & 3) == 0) { rm[th*64 + row0] = rmax0; rm[th*64 + row1] = rmax1; }
    __syncthreads();
    rmax0 = fmaxf(rm[row0], rm[64 + row0]);
    rmax1 = fmaxf(rm[row1], rm[64 + row1]);

    float sum0 = 0.0f, sum1 = 0.0f;
    #pragma unroll
    for (int nt = 0; nt < 16; nt++) {
        if (nt < ntiles) {
            #pragma unroll
            for (int e = 0; e < 4; e++) {
                float x = fmaxf(acc[nt][e] - ((e < 2) ? rmax0 : rmax1), clampv);
                float qf = floorf(x * ix0);
                float r  = x - __fmul_rn(x0i, qf);
                float z  = __fadd_rn(__fmul_rn(__fadd_rn(r, bi), r), ci);
                int   n  = 30 - (int)qf;
                float e2 = __int_as_float((n + 127) << 23);
                float ei = fmaxf(floorf(__fmul_rn(z, e2)), 0.0f);
                float t  = fminf(rintf(ei * es16), 32767.0f);
                acc[nt][e] = t;
                if (e < 2) sum0 += t; else sum1 += t;
            }
        }
    }
    sum0 += __shfl_xor_sync(0xffffffffu, sum0, 1);
    sum0 += __shfl_xor_sync(0xffffffffu, sum0, 2);
    sum1 += __shfl_xor_sync(0xffffffffu, sum1, 1);
    sum1 += __shfl_xor_sync(0xffffffffu, sum1, 2);
    float* rs = (float*)(sm + AT_RS);
    if ((lane & 3) == 0) { rs[th*64 + row0] = sum0; rs[th*64 + row1] = sum1; }
    __syncthreads();
    float fac0 = floorf(4294967296.0f / (rs[row0] + rs[64 + row0]));
    float fac1 = floorf(4294967296.0f / (rs[row1] + rs[64 + row1]));

    float oacc[8][4];
    #pragma unroll
    for (int i = 0; i < 8; i++)
        #pragma unroll
        for (int e = 0; e < 4; e++) oacc[i][e] = 0.0f;

    #pragma unroll
    for (int j = 0; j < 8; j++) {
        if (j < npair) {
            uint32_t pa[4];
            pa[0] = pkbf(floorf(__fmul_rn(acc[2*j][0],   fac0) * (1.0f/16777216.0f)),
                         floorf(__fmul_rn(acc[2*j][1],   fac0) * (1.0f/16777216.0f)));
            pa[1] = pkbf(floorf(__fmul_rn(acc[2*j][2],   fac1) * (1.0f/16777216.0f)),
                         floorf(__fmul_rn(acc[2*j][3],   fac1) * (1.0f/16777216.0f)));
            pa[2] = pkbf(floorf(__fmul_rn(acc[2*j+1][0], fac0) * (1.0f/16777216.0f)),
                         floorf(__fmul_rn(acc[2*j+1][1], fac0) * (1.0f/16777216.0f)));
            pa[3] = pkbf(floorf(__fmul_rn(acc[2*j+1][2], fac1) * (1.0f/16777216.0f)),
                         floorf(__fmul_rn(acc[2*j+1][3], fac1) * (1.0f/16777216.0f)));
            int tb2 = (th*128 + j*16)*2 + ((quad & 1) << 4);
            #pragma unroll
            for (int dt = 0; dt < 4; dt++) {
                int dr = dt*16 + ((quad >> 1) << 3) + lrow;
                uint32_t vb[4];
                LDSM4(vb, smb + AT_VT + dr*528 + tb2);
                mma_bf16(oacc[dt*2],   pa, vb[0], vb[1]);
                mma_bf16(oacc[dt*2+1], pa, vb[2], vb[3]);
            }
        }
    }

    float* ob = (float*)(sm + AT_OB);   // [64][65]
    if (th == 1) {
        #pragma unroll
        for (int nt = 0; nt < 8; nt++) {
            int d = nt*8 + ((lane & 3) << 1);
            ob[row0*65 + d]     = oacc[nt][0];
            ob[row0*65 + d + 1] = oacc[nt][1];
            ob[row1*65 + d]     = oacc[nt][2];
            ob[row1*65 + d + 1] = oacc[nt][3];
        }
    }
    __syncthreads();
    if (th == 0) {
        int m0 = b*256 + tile*64 + row0;
        int m1 = m0 + 8;
        #pragma unroll
        for (int nt = 0; nt < 8; nt++) {
            int d = nt*8 + ((lane & 3) << 1);
            float o0 = (oacc[nt][0] + ob[row0*65 + d])     * osc;
            float o1 = (oacc[nt][1] + ob[row0*65 + d + 1]) * osc;
            float o2 = (oacc[nt][2] + ob[row1*65 + d])     * osc;
            float o3 = (oacc[nt][3] + ob[row1*65 + d + 1]) * osc;
            __nv_bfloat162 hp0 = __floats2bfloat162_rn(o0, o1);
            __nv_bfloat162 lp0 = __floats2bfloat162_rn(o0 - __bfloat162float(hp0.x),
                                                       o1 - __bfloat162float(hp0.y));
            __nv_bfloat162 hp1 = __floats2bfloat162_rn(o2, o3);
            __nv_bfloat162 lp1 = __floats2bfloat162_rn(o2 - __bfloat162float(hp1.x),
                                                       o3 - __bfloat162float(hp1.y));
            *(__nv_bfloat162*)(g_x2h + (size_t)m0*384 + hd*64 + d) = hp0;
            *(__nv_bfloat162*)(g_x2l + (size_t)m0*384 + hd*64 + d) = lp0;
            *(__nv_bfloat162*)(g_x2h + (size_t)m1*384 + hd*64 + d) = hp1;
            *(__nv_bfloat162*)(g_x2l + (size_t)m1*384 + hd*64 + d) = lp1;
        }
    }
}

// ---------------- launch ----------------
extern "C" void kernel_launch(void* const* d_in, const int* in_sizes, int n_in,
                              void* d_out, int out_size) {
    (void)in_sizes; (void)n_in;
    const float* x   = (const float*)d_in[0];
    const float* xsf = (const float*)d_in[1];
    const float* Wq  = (const float*)d_in[2];
    const float* bq  = (const float*)d_in[3];
    const float* Wk  = (const float*)d_in[4];
    const float* bk  = (const float*)d_in[5];
    const float* Wv  = (const float*)d_in[6];
    const float* bv  = (const float*)d_in[7];
    const float* Wp  = (const float*)d_in[8];
    const float* bp  = (const float*)d_in[9];
    float* out = (float*)d_out;

    cudaFuncSetAttribute(k_tgemm, cudaFuncAttributeMaxDynamicSharedMemorySize, SM_TOT);
    cudaFuncSetAttribute(k_attn,  cudaFuncAttributeMaxDynamicSharedMemorySize, AT_TOT);

    k_wmax<<<576, 256>>>(Wq, Wk, Wv, Wp);
    k_pre<<<1824, 256>>>(x, xsf, Wq, bq, Wk, bk, Wv, bv, Wp, bp);
    k_tgemm<<<dim3(9, 64), 256, SM_TOT>>>(0, out, out_size);   // q,k,v projections
    k_attn<<<dim3(4, 6, 32), 256, AT_TOT>>>();                 // HMMA attention
    k_tgemm<<<dim3(3, 64), 256, SM_TOT>>>(1, out, out_size);   // output projection
}